// round 13
// baseline (speedup 1.0000x reference)
#include <cuda_runtime.h>
#include <math.h>

#define B_    32
#define T_    512
#define IN_   256
#define PRE_  512
#define LH_   512
#define NHID  1024
#define ACTH  512
#define NPOL  64
#define MTOT  (B_ * T_)      // 16384
#define G4    (4 * NHID)     // 4096

#define NBLK  128            // persistent blocks (<=148 SMs, co-resident)

// ---------------- scratch (device globals; no allocation allowed) ----------------
__device__ float g_h  [(size_t)MTOT * PRE_];
__device__ float g_u  [(size_t)MTOT * LH_];
__device__ float g_xg [(size_t)MTOT * G4];
__device__ float g_xgt[(size_t)MTOT * G4];   // transposed: [t][n][b]
__device__ float g_hs [(size_t)MTOT * NHID];
__device__ float g_a  [(size_t)MTOT * ACTH];
__device__ float g_v  [(size_t)MTOT * ACTH];
__device__ float g_hstA[B_ * NHID];
__device__ float g_hstB[B_ * NHID];
__device__ unsigned g_flags[NBLK];

__global__ void reset_flags() { if (threadIdx.x < NBLK) g_flags[threadIdx.x] = 0u; }

// ---------------- packed f32x2 helpers ----------------
__device__ __forceinline__ unsigned long long pk2(float lo, float hi) {
    unsigned long long r;
    asm("mov.b64 %0, {%1, %2};" : "=l"(r) : "f"(lo), "f"(hi));
    return r;
}
__device__ __forceinline__ void fma2(unsigned long long& d, unsigned long long a, unsigned long long b) {
    asm("fma.rn.f32x2 %0, %1, %2, %0;" : "+l"(d) : "l"(a), "l"(b));
}
__device__ __forceinline__ float2 upk(unsigned long long v) {
    float lo, hi;
    asm("mov.b64 {%0, %1}, %2;" : "=f"(lo), "=f"(hi) : "l"(v));
    return make_float2(lo, hi);
}

// ---------------- ff SGEMM: 128x64 tile, 8x4 micro, f32x2, double-buffered ----------------
#define BK  16
#define BM2 128
#define BN2 64

template<bool RELU>
__device__ __forceinline__ void sgemm128_body(
    const float* __restrict__ A, const float* __restrict__ W,
    const float* __restrict__ bias1, const float* __restrict__ bias2,
    float* __restrict__ C, int M, int N, int K, int bx, int by)
{
    __shared__ float As[2][BK][BM2 + 4];
    __shared__ float Ws[2][BK][BN2 + 4];

    const int tid = threadIdx.x;
    const int tx = tid & 15;
    const int ty = tid >> 4;
    const int m0 = by * BM2;
    const int n0 = bx * BN2;

    const int arow = tid >> 1, akq = (tid & 1) * 8;
    const int wrow = tid >> 2, wkq = (tid & 3) * 4;

    const float* Abase = &A[(size_t)(m0 + arow) * K + akq];
    const float* Wbase = &W[(size_t)(n0 + wrow) * K + wkq];

    unsigned long long acc[4][4] = {};

    {
        float4 a0 = *(const float4*)(Abase);
        float4 a1 = *(const float4*)(Abase + 4);
        float4 wv = *(const float4*)(Wbase);
        #pragma unroll
        for (int i = 0; i < 4; i++) {
            As[0][akq + i][arow]     = (&a0.x)[i];
            As[0][akq + 4 + i][arow] = (&a1.x)[i];
            Ws[0][wkq + i][wrow]     = (&wv.x)[i];
        }
    }
    __syncthreads();

    int buf = 0;
    for (int k0 = 0; k0 < K; k0 += BK) {
        float4 na0, na1, nwv;
        const bool more = (k0 + BK) < K;
        if (more) {
            na0 = *(const float4*)(Abase + k0 + BK);
            na1 = *(const float4*)(Abase + k0 + BK + 4);
            nwv = *(const float4*)(Wbase + k0 + BK);
        }

        #pragma unroll
        for (int kk = 0; kk < BK; kk++) {
            const ulonglong2* ap2 = (const ulonglong2*)&As[buf][kk][ty * 8];
            ulonglong2 aA = ap2[0];
            ulonglong2 aB = ap2[1];
            unsigned long long ap[4] = { aA.x, aA.y, aB.x, aB.y };
            float4 w4 = *(const float4*)&Ws[buf][kk][tx * 4];
            float wn[4] = {w4.x, w4.y, w4.z, w4.w};
            #pragma unroll
            for (int j = 0; j < 4; j++) {
                unsigned long long wd = pk2(wn[j], wn[j]);
                #pragma unroll
                for (int p = 0; p < 4; p++) fma2(acc[p][j], ap[p], wd);
            }
        }

        if (more) {
            const int nb = buf ^ 1;
            #pragma unroll
            for (int i = 0; i < 4; i++) {
                As[nb][akq + i][arow]     = (&na0.x)[i];
                As[nb][akq + 4 + i][arow] = (&na1.x)[i];
                Ws[nb][wkq + i][wrow]     = (&nwv.x)[i];
            }
            __syncthreads();
        }
        buf ^= 1;
    }

    float4 bv = *(const float4*)&bias1[n0 + tx * 4];
    if (bias2) {
        float4 b2 = *(const float4*)&bias2[n0 + tx * 4];
        bv.x += b2.x; bv.y += b2.y; bv.z += b2.z; bv.w += b2.w;
    }
    float bn[4] = {bv.x, bv.y, bv.z, bv.w};

    #pragma unroll
    for (int p = 0; p < 4; p++) {
        float2 u0 = upk(acc[p][0]), u1 = upk(acc[p][1]);
        float2 u2 = upk(acc[p][2]), u3 = upk(acc[p][3]);
        float4 lo = {u0.x + bn[0], u1.x + bn[1], u2.x + bn[2], u3.x + bn[3]};
        float4 hi = {u0.y + bn[0], u1.y + bn[1], u2.y + bn[2], u3.y + bn[3]};
        if (RELU) {
            lo.x = fmaxf(lo.x, 0.f); lo.y = fmaxf(lo.y, 0.f);
            lo.z = fmaxf(lo.z, 0.f); lo.w = fmaxf(lo.w, 0.f);
            hi.x = fmaxf(hi.x, 0.f); hi.y = fmaxf(hi.y, 0.f);
            hi.z = fmaxf(hi.z, 0.f); hi.w = fmaxf(hi.w, 0.f);
        }
        *(float4*)&C[(size_t)(m0 + ty * 8 + 2 * p)     * N + n0 + tx * 4] = lo;
        *(float4*)&C[(size_t)(m0 + ty * 8 + 2 * p + 1) * N + n0 + tx * 4] = hi;
    }
}

template<bool RELU>
__global__ void __launch_bounds__(256)
sgemm128(const float* __restrict__ A, const float* __restrict__ W,
         const float* __restrict__ bias1, const float* __restrict__ bias2,
         float* __restrict__ C, int M, int N, int K)
{
    sgemm128_body<RELU>(A, W, bias1, bias2, C, M, N, K, blockIdx.x, blockIdx.y);
}

// fused act0/val0 head GEMM: blockIdx.z selects (W, bias, C)
__global__ void __launch_bounds__(256)
sgemm128_dual(const float* __restrict__ A,
              const float* __restrict__ Wa, const float* __restrict__ ba, float* __restrict__ Ca,
              const float* __restrict__ Wv, const float* __restrict__ bv, float* __restrict__ Cv,
              int M, int N, int K)
{
    const float* W = blockIdx.z ? Wv : Wa;
    const float* b = blockIdx.z ? bv : ba;
    float*       C = blockIdx.z ? Cv : Ca;
    sgemm128_body<true>(A, W, b, nullptr, C, M, N, K, blockIdx.x, blockIdx.y);
}

// ---------------- xg transpose: [b*T+t][n] -> [t][n][b] ----------------
__global__ void __launch_bounds__(256)
transpose_xg(const float* __restrict__ in, float* __restrict__ out)
{
    __shared__ float s[32][132];
    const int t  = blockIdx.y;
    const int n0 = blockIdx.x * 128;
    const int tid = threadIdx.x;

    {
        const int b  = tid >> 3;
        const int nq = (tid & 7) * 16;
        const float* src = in + ((size_t)b * T_ + t) * G4 + n0 + nq;
        #pragma unroll
        for (int i = 0; i < 4; i++) {
            float4 v = *(const float4*)(src + 4 * i);
            *(float4*)&s[b][nq + 4 * i] = v;
        }
    }
    __syncthreads();

    {
        const int n  = tid >> 1;
        const int bh = (tid & 1) * 16;
        float* dst = out + ((size_t)t * G4 + n0 + n) * 32 + bh;
        #pragma unroll
        for (int i = 0; i < 4; i++) {
            float4 v;
            v.x = s[bh + 4 * i + 0][n];
            v.y = s[bh + 4 * i + 1][n];
            v.z = s[bh + 4 * i + 2][n];
            v.w = s[bh + 4 * i + 3][n];
            *(float4*)(dst + 4 * i) = v;
        }
    }
}

// ---------------- grid-wide barrier (init only) ----------------
__device__ __forceinline__ void grid_bar2(int tid, unsigned epoch) {
    __threadfence();
    __syncthreads();
    if (tid == 0) atomicExch(&g_flags[blockIdx.x], epoch);
    if (tid < NBLK) {
        while (__ldcg(&g_flags[tid]) < epoch) __nanosleep(16);
    }
    __syncthreads();
}

// ---------------- persistent LSTM recurrence, weights in registers ----------------
#define HST_F  (8 * 32 * 128)
#define RED_F  (8 * 32 * 33 + 32)
#define RSMEM_BYTES ((HST_F + RED_F) * 4)

__global__ void __launch_bounds__(256, 1)
lstm_persist(const float* __restrict__ Whh, const float* __restrict__ xgt,
             float* __restrict__ hA, float* __restrict__ hB, float* __restrict__ hs)
{
    extern __shared__ float sm[];
    float* hst = sm;                    // [warp][32 b][128 k]
    float* red = sm + HST_F;            // [(w*32 + r)*33 + b]

    const int tid  = threadIdx.x;
    const int lane = tid & 31;
    const int w    = tid >> 5;
    const int bid  = blockIdx.x;

    // ---- weight registers: lane = gate-row, warp = K-slice ----
    const int uo   = lane >> 2;
    const int gate = lane & 3;
    const float* wrow = Whh + ((size_t)(gate * NHID + bid * 8 + uo)) * NHID + w * 128;
    ulonglong2 wk[32];
    #pragma unroll
    for (int q = 0; q < 32; q++)
        wk[q] = *(const ulonglong2*)(wrow + q * 4);

    // ---- cell role: thread = (unit u = w, batch b = lane) ----
    const int u = w;
    const int b = lane;
    const int jg = bid * 8 + u;
    float c = 0.0f;
    hA[b * NHID + jg] = 0.0f;

    grid_bar2(tid, 1u);

    float* myh = hst + w * 4096;

    for (int t = 0; t < T_; t++) {
        const float* hin = (t & 1) ? hB : hA;
        float*       hot = (t & 1) ? hA : hB;

        // gate biases — transposed layout, 1 coalesced wavefront each
        const float* xr = xgt + ((size_t)t * G4 + jg) * 32 + b;
        float xi = __ldg(xr);
        float xf = __ldg(xr + (size_t)NHID * 32);
        float xG = __ldg(xr + (size_t)2 * NHID * 32);
        float xo = __ldg(xr + (size_t)3 * NHID * 32);

        const float* src = hin + w * 128 + lane * 4;

        // stage quarter 0 (batches 0..7)
        {
            float4 v[8];
            #pragma unroll
            for (int i = 0; i < 8; i++)
                v[i] = __ldcg((const float4*)(src + (size_t)i * NHID));
            #pragma unroll
            for (int i = 0; i < 8; i++)
                *(float4*)(myh + i * 128 + lane * 4) = v[i];
        }
        __syncwarp();

        // pipelined quarters
        #pragma unroll 1
        for (int qt = 0; qt < 4; qt++) {
            float4 nv[8];
            if (qt < 3) {
                #pragma unroll
                for (int i = 0; i < 8; i++)
                    nv[i] = __ldcg((const float4*)(src + (size_t)((qt + 1) * 8 + i) * NHID));
            }

            #pragma unroll 1
            for (int bq = 0; bq < 8; bq++) {
                const int bb = qt * 8 + bq;
                const float* hb = myh + bb * 128;
                unsigned long long a0 = 0, a1 = 0;
                #pragma unroll
                for (int q = 0; q < 32; q++) {
                    ulonglong2 hv = *(const ulonglong2*)(hb + q * 4);
                    fma2(a0, wk[q].x, hv.x);
                    fma2(a1, wk[q].y, hv.y);
                }
                float2 p0 = upk(a0), p1 = upk(a1);
                red[(w * 32 + lane) * 33 + bb] = (p0.x + p0.y) + (p1.x + p1.y);
            }

            if (qt < 3) {
                #pragma unroll
                for (int i = 0; i < 8; i++)
                    *(float4*)(myh + ((qt + 1) * 8 + i) * 128 + lane * 4) = nv[i];
                __syncwarp();
            }
        }
        __syncthreads();

        // ---- reduce 8 K-partials + cell update ----
        float s0 = 0.f, s1 = 0.f, s2 = 0.f, s3 = 0.f;
        #pragma unroll
        for (int ww = 0; ww < 8; ww++) {
            const float* rb = red + (ww * 32 + u * 4) * 33 + b;
            s0 += rb[0];
            s1 += rb[33];
            s2 += rb[66];
            s3 += rb[99];
        }
        float gi = s0 + xi, gf = s1 + xf, gg = s2 + xG, go = s3 + xo;

        float si = 1.0f / (1.0f + expf(-gi));
        float sf = 1.0f / (1.0f + expf(-gf));
        float so = 1.0f / (1.0f + expf(-go));

        c = sf * c + si * tanhf(gg);
        float h = so * tanhf(c);

        // h for next step: must be fenced before the flag
        __stcg(&hot[b * NHID + jg], h);

        // ---- grid barrier with history store hidden under the poll ----
        __threadfence();
        __syncthreads();
        if (tid == 0) atomicExch(&g_flags[bid], (unsigned)(t + 2));
        // hs is only read after this kernel completes — not fenced, hidden here
        hs[((size_t)b * T_ + t) * NHID + jg] = h;
        if (tid < NBLK) {
            while (__ldcg(&g_flags[tid]) < (unsigned)(t + 2)) __nanosleep(16);
        }
        __syncthreads();
    }
}

// ---------------- softmax over last dim (64) in place ----------------
__global__ void softmax64(float* __restrict__ logits) {
    const int row  = blockIdx.x * 4 + (threadIdx.x >> 5);
    const int lane = threadIdx.x & 31;
    float* p = logits + (size_t)row * NPOL;
    float v0 = p[lane], v1 = p[lane + 32];
    float m = fmaxf(v0, v1);
    #pragma unroll
    for (int off = 16; off > 0; off >>= 1)
        m = fmaxf(m, __shfl_xor_sync(0xffffffffu, m, off));
    float e0 = expf(v0 - m), e1 = expf(v1 - m);
    float sden = e0 + e1;
    #pragma unroll
    for (int off = 16; off > 0; off >>= 1)
        sden += __shfl_xor_sync(0xffffffffu, sden, off);
    float inv = 1.0f / sden;
    p[lane] = e0 * inv;
    p[lane + 32] = e1 * inv;
}

// ---------------- value head: out[m] = dot(V[m,:512], w) + b[0] ----------------
__global__ void matvec_val(const float* __restrict__ V, const float* __restrict__ w,
                           const float* __restrict__ bias, float* __restrict__ out) {
    const int row  = blockIdx.x * 8 + (threadIdx.x >> 5);
    const int lane = threadIdx.x & 31;
    const float* vr = V + (size_t)row * ACTH;
    float s = 0.0f;
    #pragma unroll
    for (int q = 0; q < 4; q++) {
        int k = q * 128 + lane * 4;
        float4 a = *(const float4*)&vr[k];
        float4 b = *(const float4*)&w[k];
        s = fmaf(a.x, b.x, s); s = fmaf(a.y, b.y, s);
        s = fmaf(a.z, b.z, s); s = fmaf(a.w, b.w, s);
    }
    #pragma unroll
    for (int off = 16; off > 0; off >>= 1)
        s += __shfl_xor_sync(0xffffffffu, s, off);
    if (lane == 0) out[row] = s + bias[0];
}

// ---------------- launch ----------------
extern "C" void kernel_launch(void* const* d_in, const int* in_sizes, int n_in,
                              void* d_out, int out_size) {
    const float* x        = (const float*)d_in[0];
    const float* pre_W0   = (const float*)d_in[1];
    const float* pre_b0   = (const float*)d_in[2];
    const float* pre_W1   = (const float*)d_in[3];
    const float* pre_b1   = (const float*)d_in[4];
    const float* w_ih     = (const float*)d_in[5];
    const float* w_hh     = (const float*)d_in[6];
    const float* b_ih     = (const float*)d_in[7];
    const float* b_hh     = (const float*)d_in[8];
    const float* act_W0   = (const float*)d_in[9];
    const float* act_b0   = (const float*)d_in[10];
    const float* act_W1   = (const float*)d_in[11];
    const float* act_b1   = (const float*)d_in[12];
    const float* val_W0   = (const float*)d_in[13];
    const float* val_b0   = (const float*)d_in[14];
    const float* val_W1   = (const float*)d_in[15];
    const float* val_b1   = (const float*)d_in[16];

    float* out_probs = (float*)d_out;
    float* out_value = (float*)d_out + (size_t)MTOT * NPOL;

    float *pH, *pU, *pXG, *pXGT, *pHS, *pA, *pV, *pHA, *pHB;
    cudaGetSymbolAddress((void**)&pH,   g_h);
    cudaGetSymbolAddress((void**)&pU,   g_u);
    cudaGetSymbolAddress((void**)&pXG,  g_xg);
    cudaGetSymbolAddress((void**)&pXGT, g_xgt);
    cudaGetSymbolAddress((void**)&pHS,  g_hs);
    cudaGetSymbolAddress((void**)&pA,   g_a);
    cudaGetSymbolAddress((void**)&pV,   g_v);
    cudaGetSymbolAddress((void**)&pHA,  g_hstA);
    cudaGetSymbolAddress((void**)&pHB,  g_hstB);

    cudaFuncSetAttribute(lstm_persist, cudaFuncAttributeMaxDynamicSharedMemorySize, RSMEM_BYTES);

    reset_flags<<<1, 128>>>();

    // pre_dnn
    sgemm128<true ><<<dim3(PRE_ / BN2, MTOT / BM2), 256>>>(x,  pre_W0, pre_b0, nullptr, pH, MTOT, PRE_, IN_);
    sgemm128<false><<<dim3(LH_  / BN2, MTOT / BM2), 256>>>(pH, pre_W1, pre_b1, nullptr, pU, MTOT, LH_, PRE_);

    // input contribution to gates (+ both biases)
    sgemm128<false><<<dim3(G4 / BN2, MTOT / BM2), 256>>>(pU, w_ih, b_ih, b_hh, pXG, MTOT, G4, LH_);

    // transpose xg to [t][n][b] for coalesced per-step reads
    transpose_xg<<<dim3(G4 / 128, T_), 256>>>(pXG, pXGT);

    // persistent recurrence (one launch for all 512 steps)
    lstm_persist<<<NBLK, 256, RSMEM_BYTES>>>(w_hh, pXGT, pHA, pHB, pHS);

    // fused first layers of both heads (relu)
    sgemm128_dual<<<dim3(ACTH / BN2, MTOT / BM2, 2), 256>>>(
        pHS, act_W0, act_b0, pA, val_W0, val_b0, pV, MTOT, ACTH, NHID);

    // policy logits + softmax
    sgemm128<false><<<dim3(NPOL / BN2, MTOT / BM2), 256>>>(pA, act_W1, act_b1, nullptr, out_probs, MTOT, NPOL, ACTH);
    softmax64<<<MTOT / 4, 128>>>(out_probs);

    // value output
    matvec_val<<<MTOT / 8, 256>>>(pV, val_W1, val_b1, out_value);
}

// round 14
// speedup vs baseline: 1.0465x; 1.0465x over previous
#include <cuda_runtime.h>
#include <math.h>

#define B_    32
#define T_    512
#define IN_   256
#define PRE_  512
#define LH_   512
#define NHID  1024
#define ACTH  512
#define NPOL  64
#define MTOT  (B_ * T_)      // 16384
#define G4    (4 * NHID)     // 4096

#define NBLK  128            // persistent blocks (<=148 SMs, co-resident)

// ---------------- scratch (device globals; no allocation allowed) ----------------
__device__ float g_h [(size_t)MTOT * PRE_];
__device__ float g_u [(size_t)MTOT * LH_];
__device__ float g_xg[(size_t)MTOT * G4];
__device__ float g_hs[(size_t)MTOT * NHID];
__device__ float g_a [(size_t)MTOT * ACTH];
__device__ float g_v [(size_t)MTOT * ACTH];
__device__ float g_hstA[B_ * NHID];
__device__ float g_hstB[B_ * NHID];
__device__ unsigned g_flags[NBLK];

__global__ void reset_flags() { if (threadIdx.x < NBLK) g_flags[threadIdx.x] = 0u; }

// ---------------- packed f32x2 helpers ----------------
__device__ __forceinline__ unsigned long long pk2(float lo, float hi) {
    unsigned long long r;
    asm("mov.b64 %0, {%1, %2};" : "=l"(r) : "f"(lo), "f"(hi));
    return r;
}
__device__ __forceinline__ void fma2(unsigned long long& d, unsigned long long a, unsigned long long b) {
    asm("fma.rn.f32x2 %0, %1, %2, %0;" : "+l"(d) : "l"(a), "l"(b));
}
__device__ __forceinline__ float2 upk(unsigned long long v) {
    float lo, hi;
    asm("mov.b64 {%0, %1}, %2;" : "=f"(lo), "=f"(hi) : "l"(v));
    return make_float2(lo, hi);
}

// ---------------- ff SGEMM: 128x64 tile, 8x4 micro, f32x2, double-buffered ----------------
#define BK  16
#define BM2 128
#define BN2 64

template<bool RELU>
__device__ __forceinline__ void sgemm128_body(
    const float* __restrict__ A, const float* __restrict__ W,
    const float* __restrict__ bias1, const float* __restrict__ bias2,
    float* __restrict__ C, int M, int N, int K, int bx, int by)
{
    __shared__ float As[2][BK][BM2 + 4];
    __shared__ float Ws[2][BK][BN2 + 4];

    const int tid = threadIdx.x;
    const int tx = tid & 15;
    const int ty = tid >> 4;
    const int m0 = by * BM2;
    const int n0 = bx * BN2;

    const int arow = tid >> 1, akq = (tid & 1) * 8;
    const int wrow = tid >> 2, wkq = (tid & 3) * 4;

    const float* Abase = &A[(size_t)(m0 + arow) * K + akq];
    const float* Wbase = &W[(size_t)(n0 + wrow) * K + wkq];

    unsigned long long acc[4][4] = {};

    {
        float4 a0 = *(const float4*)(Abase);
        float4 a1 = *(const float4*)(Abase + 4);
        float4 wv = *(const float4*)(Wbase);
        #pragma unroll
        for (int i = 0; i < 4; i++) {
            As[0][akq + i][arow]     = (&a0.x)[i];
            As[0][akq + 4 + i][arow] = (&a1.x)[i];
            Ws[0][wkq + i][wrow]     = (&wv.x)[i];
        }
    }
    __syncthreads();

    int buf = 0;
    for (int k0 = 0; k0 < K; k0 += BK) {
        float4 na0, na1, nwv;
        const bool more = (k0 + BK) < K;
        if (more) {
            na0 = *(const float4*)(Abase + k0 + BK);
            na1 = *(const float4*)(Abase + k0 + BK + 4);
            nwv = *(const float4*)(Wbase + k0 + BK);
        }

        #pragma unroll
        for (int kk = 0; kk < BK; kk++) {
            const ulonglong2* ap2 = (const ulonglong2*)&As[buf][kk][ty * 8];
            ulonglong2 aA = ap2[0];
            ulonglong2 aB = ap2[1];
            unsigned long long ap[4] = { aA.x, aA.y, aB.x, aB.y };
            float4 w4 = *(const float4*)&Ws[buf][kk][tx * 4];
            float wn[4] = {w4.x, w4.y, w4.z, w4.w};
            #pragma unroll
            for (int j = 0; j < 4; j++) {
                unsigned long long wd = pk2(wn[j], wn[j]);
                #pragma unroll
                for (int p = 0; p < 4; p++) fma2(acc[p][j], ap[p], wd);
            }
        }

        if (more) {
            const int nb = buf ^ 1;
            #pragma unroll
            for (int i = 0; i < 4; i++) {
                As[nb][akq + i][arow]     = (&na0.x)[i];
                As[nb][akq + 4 + i][arow] = (&na1.x)[i];
                Ws[nb][wkq + i][wrow]     = (&nwv.x)[i];
            }
            __syncthreads();
        }
        buf ^= 1;
    }

    float4 bv = *(const float4*)&bias1[n0 + tx * 4];
    if (bias2) {
        float4 b2 = *(const float4*)&bias2[n0 + tx * 4];
        bv.x += b2.x; bv.y += b2.y; bv.z += b2.z; bv.w += b2.w;
    }
    float bn[4] = {bv.x, bv.y, bv.z, bv.w};

    #pragma unroll
    for (int p = 0; p < 4; p++) {
        float2 u0 = upk(acc[p][0]), u1 = upk(acc[p][1]);
        float2 u2 = upk(acc[p][2]), u3 = upk(acc[p][3]);
        float4 lo = {u0.x + bn[0], u1.x + bn[1], u2.x + bn[2], u3.x + bn[3]};
        float4 hi = {u0.y + bn[0], u1.y + bn[1], u2.y + bn[2], u3.y + bn[3]};
        if (RELU) {
            lo.x = fmaxf(lo.x, 0.f); lo.y = fmaxf(lo.y, 0.f);
            lo.z = fmaxf(lo.z, 0.f); lo.w = fmaxf(lo.w, 0.f);
            hi.x = fmaxf(hi.x, 0.f); hi.y = fmaxf(hi.y, 0.f);
            hi.z = fmaxf(hi.z, 0.f); hi.w = fmaxf(hi.w, 0.f);
        }
        *(float4*)&C[(size_t)(m0 + ty * 8 + 2 * p)     * N + n0 + tx * 4] = lo;
        *(float4*)&C[(size_t)(m0 + ty * 8 + 2 * p + 1) * N + n0 + tx * 4] = hi;
    }
}

template<bool RELU>
__global__ void __launch_bounds__(256)
sgemm128(const float* __restrict__ A, const float* __restrict__ W,
         const float* __restrict__ bias1, const float* __restrict__ bias2,
         float* __restrict__ C, int M, int N, int K)
{
    sgemm128_body<RELU>(A, W, bias1, bias2, C, M, N, K, blockIdx.x, blockIdx.y);
}

// fused act0/val0 head GEMM: blockIdx.z selects (W, bias, C)
__global__ void __launch_bounds__(256)
sgemm128_dual(const float* __restrict__ A,
              const float* __restrict__ Wa, const float* __restrict__ ba, float* __restrict__ Ca,
              const float* __restrict__ Wv, const float* __restrict__ bv, float* __restrict__ Cv,
              int M, int N, int K)
{
    const float* W = blockIdx.z ? Wv : Wa;
    const float* b = blockIdx.z ? bv : ba;
    float*       C = blockIdx.z ? Cv : Ca;
    sgemm128_body<true>(A, W, b, nullptr, C, M, N, K, blockIdx.x, blockIdx.y);
}

// ---------------- init barrier (one-shot) ----------------
__device__ __forceinline__ void grid_bar_init(int tid) {
    __threadfence();
    __syncthreads();
    if (tid == 0) atomicExch(&g_flags[blockIdx.x], 1u);
    if (tid < NBLK) {
        while (__ldcg(&g_flags[tid]) < 1u) __nanosleep(16);
    }
    __syncthreads();
}

// ---------------- persistent LSTM recurrence, weights in registers ----------------
// Flag protocol: flags[bid] = t+2 means block bid has completed step t (h(t) stored
// and fenced). Step t staging of h(t-1) requires producer flags >= t+1. The WAR
// hazard (h(t) overwrites h(t-2)'s buffer) requires ALL flags >= t+1, checked
// lazily right before the store — one step behind, so usually zero wait.
// Warp w consumes k-slice [w*128, w*128+128) = units from blocks [16w, 16w+16).
#define HST_F  (8 * 32 * 128)
#define RED_F  (8 * 32 * 33 + 32)
#define RSMEM_BYTES ((HST_F + RED_F) * 4)

__global__ void __launch_bounds__(256, 1)
lstm_persist(const float* __restrict__ Whh, const float* __restrict__ xg,
             float* __restrict__ hA, float* __restrict__ hB, float* __restrict__ hs)
{
    extern __shared__ float sm[];
    float* hst = sm;                    // [warp][32 b][128 k]
    float* red = sm + HST_F;            // [(w*32 + r)*33 + b]

    const int tid  = threadIdx.x;
    const int lane = tid & 31;
    const int w    = tid >> 5;
    const int bid  = blockIdx.x;

    // ---- weight registers: lane = gate-row, warp = K-slice ----
    const int uo   = lane >> 2;
    const int gate = lane & 3;
    const float* wrow = Whh + ((size_t)(gate * NHID + bid * 8 + uo)) * NHID + w * 128;
    ulonglong2 wk[32];
    #pragma unroll
    for (int q = 0; q < 32; q++)
        wk[q] = *(const ulonglong2*)(wrow + q * 4);

    // ---- cell role: thread = (unit u = w, batch b = lane) ----
    const int u = w;
    const int b = lane;
    const int jg = bid * 8 + u;
    float c = 0.0f;
    hA[b * NHID + jg] = 0.0f;

    grid_bar_init(tid);   // all flags = 1 (h(-1) ready)

    float* myh = hst + w * 4096;
    const int myprod = w * 16 + (lane & 15);   // this lane's producer flag to poll

    for (int t = 0; t < T_; t++) {
        const float* hin = (t & 1) ? hB : hA;
        float*       hot = (t & 1) ? hA : hB;
        const unsigned ep = (unsigned)(t + 1);   // producers completed step t-1

        // gate biases (independent of h; issued before any waiting)
        const float* xr = xg + ((size_t)b * T_ + t) * G4 + jg;
        float xi = __ldg(xr);
        float xf = __ldg(xr + NHID);
        float xG = __ldg(xr + 2 * NHID);
        float xo = __ldg(xr + 3 * NHID);

        // ---- forward wait: only THIS warp's 16 producers ----
        while (__ldcg(&g_flags[myprod]) < ep) __nanosleep(16);
        __syncwarp();

        const float* src = hin + w * 128 + lane * 4;

        // stage quarter 0 (batches 0..7)
        {
            float4 v[8];
            #pragma unroll
            for (int i = 0; i < 8; i++)
                v[i] = __ldcg((const float4*)(src + (size_t)i * NHID));
            #pragma unroll
            for (int i = 0; i < 8; i++)
                *(float4*)(myh + i * 128 + lane * 4) = v[i];
        }
        __syncwarp();

        // pipelined quarters
        #pragma unroll 1
        for (int qt = 0; qt < 4; qt++) {
            float4 nv[8];
            if (qt < 3) {
                #pragma unroll
                for (int i = 0; i < 8; i++)
                    nv[i] = __ldcg((const float4*)(src + (size_t)((qt + 1) * 8 + i) * NHID));
            }

            #pragma unroll 1
            for (int bq = 0; bq < 8; bq++) {
                const int bb = qt * 8 + bq;
                const float* hb = myh + bb * 128;
                unsigned long long a0 = 0, a1 = 0;
                #pragma unroll
                for (int q = 0; q < 32; q++) {
                    ulonglong2 hv = *(const ulonglong2*)(hb + q * 4);
                    fma2(a0, wk[q].x, hv.x);
                    fma2(a1, wk[q].y, hv.y);
                }
                float2 p0 = upk(a0), p1 = upk(a1);
                red[(w * 32 + lane) * 33 + bb] = (p0.x + p0.y) + (p1.x + p1.y);
            }

            if (qt < 3) {
                #pragma unroll
                for (int i = 0; i < 8; i++)
                    *(float4*)(myh + ((qt + 1) * 8 + i) * 128 + lane * 4) = nv[i];
                __syncwarp();
            }
        }
        __syncthreads();

        // ---- reduce 8 K-partials + cell update ----
        float s0 = 0.f, s1 = 0.f, s2 = 0.f, s3 = 0.f;
        #pragma unroll
        for (int ww = 0; ww < 8; ww++) {
            const float* rb = red + (ww * 32 + u * 4) * 33 + b;
            s0 += rb[0];
            s1 += rb[33];
            s2 += rb[66];
            s3 += rb[99];
        }
        float gi = s0 + xi, gf = s1 + xf, gg = s2 + xG, go = s3 + xo;

        float si = 1.0f / (1.0f + expf(-gi));
        float sf = 1.0f / (1.0f + expf(-gf));
        float so = 1.0f / (1.0f + expf(-go));

        c = sf * c + si * tanhf(gg);
        float h = so * tanhf(c);

        // ---- lazy WAR-hazard check (one step behind; usually zero wait) ----
        if (tid < NBLK) {
            while (__ldcg(&g_flags[tid]) < ep) __nanosleep(16);
        }
        __syncthreads();

        // h for next step + history
        __stcg(&hot[b * NHID + jg], h);
        hs[((size_t)b * T_ + t) * NHID + jg] = h;

        __threadfence();
        __syncthreads();
        if (tid == 0) atomicExch(&g_flags[bid], (unsigned)(t + 2));
    }
}

// ---------------- softmax over last dim (64) in place ----------------
__global__ void softmax64(float* __restrict__ logits) {
    const int row  = blockIdx.x * 4 + (threadIdx.x >> 5);
    const int lane = threadIdx.x & 31;
    float* p = logits + (size_t)row * NPOL;
    float v0 = p[lane], v1 = p[lane + 32];
    float m = fmaxf(v0, v1);
    #pragma unroll
    for (int off = 16; off > 0; off >>= 1)
        m = fmaxf(m, __shfl_xor_sync(0xffffffffu, m, off));
    float e0 = expf(v0 - m), e1 = expf(v1 - m);
    float sden = e0 + e1;
    #pragma unroll
    for (int off = 16; off > 0; off >>= 1)
        sden += __shfl_xor_sync(0xffffffffu, sden, off);
    float inv = 1.0f / sden;
    p[lane] = e0 * inv;
    p[lane + 32] = e1 * inv;
}

// ---------------- value head: out[m] = dot(V[m,:512], w) + b[0] ----------------
__global__ void matvec_val(const float* __restrict__ V, const float* __restrict__ w,
                           const float* __restrict__ bias, float* __restrict__ out) {
    const int row  = blockIdx.x * 8 + (threadIdx.x >> 5);
    const int lane = threadIdx.x & 31;
    const float* vr = V + (size_t)row * ACTH;
    float s = 0.0f;
    #pragma unroll
    for (int q = 0; q < 4; q++) {
        int k = q * 128 + lane * 4;
        float4 a = *(const float4*)&vr[k];
        float4 b = *(const float4*)&w[k];
        s = fmaf(a.x, b.x, s); s = fmaf(a.y, b.y, s);
        s = fmaf(a.z, b.z, s); s = fmaf(a.w, b.w, s);
    }
    #pragma unroll
    for (int off = 16; off > 0; off >>= 1)
        s += __shfl_xor_sync(0xffffffffu, s, off);
    if (lane == 0) out[row] = s + bias[0];
}

// ---------------- launch ----------------
extern "C" void kernel_launch(void* const* d_in, const int* in_sizes, int n_in,
                              void* d_out, int out_size) {
    const float* x        = (const float*)d_in[0];
    const float* pre_W0   = (const float*)d_in[1];
    const float* pre_b0   = (const float*)d_in[2];
    const float* pre_W1   = (const float*)d_in[3];
    const float* pre_b1   = (const float*)d_in[4];
    const float* w_ih     = (const float*)d_in[5];
    const float* w_hh     = (const float*)d_in[6];
    const float* b_ih     = (const float*)d_in[7];
    const float* b_hh     = (const float*)d_in[8];
    const float* act_W0   = (const float*)d_in[9];
    const float* act_b0   = (const float*)d_in[10];
    const float* act_W1   = (const float*)d_in[11];
    const float* act_b1   = (const float*)d_in[12];
    const float* val_W0   = (const float*)d_in[13];
    const float* val_b0   = (const float*)d_in[14];
    const float* val_W1   = (const float*)d_in[15];
    const float* val_b1   = (const float*)d_in[16];

    float* out_probs = (float*)d_out;
    float* out_value = (float*)d_out + (size_t)MTOT * NPOL;

    float *pH, *pU, *pXG, *pHS, *pA, *pV, *pHA, *pHB;
    cudaGetSymbolAddress((void**)&pH,  g_h);
    cudaGetSymbolAddress((void**)&pU,  g_u);
    cudaGetSymbolAddress((void**)&pXG, g_xg);
    cudaGetSymbolAddress((void**)&pHS, g_hs);
    cudaGetSymbolAddress((void**)&pA,  g_a);
    cudaGetSymbolAddress((void**)&pV,  g_v);
    cudaGetSymbolAddress((void**)&pHA, g_hstA);
    cudaGetSymbolAddress((void**)&pHB, g_hstB);

    cudaFuncSetAttribute(lstm_persist, cudaFuncAttributeMaxDynamicSharedMemorySize, RSMEM_BYTES);

    reset_flags<<<1, 128>>>();

    // pre_dnn
    sgemm128<true ><<<dim3(PRE_ / BN2, MTOT / BM2), 256>>>(x,  pre_W0, pre_b0, nullptr, pH, MTOT, PRE_, IN_);
    sgemm128<false><<<dim3(LH_  / BN2, MTOT / BM2), 256>>>(pH, pre_W1, pre_b1, nullptr, pU, MTOT, LH_, PRE_);

    // input contribution to gates (+ both biases)
    sgemm128<false><<<dim3(G4 / BN2, MTOT / BM2), 256>>>(pU, w_ih, b_ih, b_hh, pXG, MTOT, G4, LH_);

    // persistent recurrence (one launch for all 512 steps)
    lstm_persist<<<NBLK, 256, RSMEM_BYTES>>>(w_hh, pXG, pHA, pHB, pHS);

    // fused first layers of both heads (relu)
    sgemm128_dual<<<dim3(ACTH / BN2, MTOT / BM2, 2), 256>>>(
        pHS, act_W0, act_b0, pA, val_W0, val_b0, pV, MTOT, ACTH, NHID);

    // policy logits + softmax
    sgemm128<false><<<dim3(NPOL / BN2, MTOT / BM2), 256>>>(pA, act_W1, act_b1, nullptr, out_probs, MTOT, NPOL, ACTH);
    softmax64<<<MTOT / 4, 128>>>(out_probs);

    // value output
    matvec_val<<<MTOT / 8, 256>>>(pV, val_W1, val_b1, out_value);
}

// round 15
// speedup vs baseline: 1.0745x; 1.0267x over previous
#include <cuda_runtime.h>
#include <math.h>

#define B_    32
#define T_    512
#define IN_   256
#define PRE_  512
#define LH_   512
#define NHID  1024
#define ACTH  512
#define NPOL  64
#define MTOT  (B_ * T_)      // 16384
#define G4    (4 * NHID)     // 4096

#define NBLK  128            // persistent blocks (<=148 SMs, co-resident)

// ---------------- scratch (device globals; no allocation allowed) ----------------
__device__ float g_h [(size_t)MTOT * PRE_];
__device__ float g_u [(size_t)MTOT * LH_];
__device__ float g_xg[(size_t)MTOT * G4];
__device__ float g_hs[(size_t)MTOT * NHID];
__device__ float g_a [(size_t)MTOT * ACTH];
__device__ float g_v [(size_t)MTOT * ACTH];
__device__ float g_hstA[B_ * NHID];
__device__ float g_hstB[B_ * NHID];
__device__ unsigned g_flags[NBLK];

__global__ void reset_flags() { if (threadIdx.x < NBLK) g_flags[threadIdx.x] = 0u; }

// ---------------- packed f32x2 helpers ----------------
__device__ __forceinline__ unsigned long long pk2(float lo, float hi) {
    unsigned long long r;
    asm("mov.b64 %0, {%1, %2};" : "=l"(r) : "f"(lo), "f"(hi));
    return r;
}
__device__ __forceinline__ void fma2(unsigned long long& d, unsigned long long a, unsigned long long b) {
    asm("fma.rn.f32x2 %0, %1, %2, %0;" : "+l"(d) : "l"(a), "l"(b));
}
__device__ __forceinline__ float2 upk(unsigned long long v) {
    float lo, hi;
    asm("mov.b64 {%0, %1}, %2;" : "=f"(lo), "=f"(hi) : "l"(v));
    return make_float2(lo, hi);
}

// release-publish: orders the whole block's prior stores (after bar.sync) gpu-wide.
__device__ __forceinline__ void flag_release(unsigned* addr, unsigned val) {
    unsigned old;
    asm volatile("atom.release.gpu.global.exch.b32 %0, [%1], %2;"
                 : "=r"(old) : "l"(addr), "r"(val) : "memory");
}

// ---------------- ff SGEMM: 128x64 tile, 8x4 micro, f32x2, double-buffered ----------------
#define BK  16
#define BM2 128
#define BN2 64

template<bool RELU>
__device__ __forceinline__ void sgemm128_body(
    const float* __restrict__ A, const float* __restrict__ W,
    const float* __restrict__ bias1, const float* __restrict__ bias2,
    float* __restrict__ C, int M, int N, int K, int bx, int by)
{
    __shared__ float As[2][BK][BM2 + 4];
    __shared__ float Ws[2][BK][BN2 + 4];

    const int tid = threadIdx.x;
    const int tx = tid & 15;
    const int ty = tid >> 4;
    const int m0 = by * BM2;
    const int n0 = bx * BN2;

    const int arow = tid >> 1, akq = (tid & 1) * 8;
    const int wrow = tid >> 2, wkq = (tid & 3) * 4;

    const float* Abase = &A[(size_t)(m0 + arow) * K + akq];
    const float* Wbase = &W[(size_t)(n0 + wrow) * K + wkq];

    unsigned long long acc[4][4] = {};

    {
        float4 a0 = *(const float4*)(Abase);
        float4 a1 = *(const float4*)(Abase + 4);
        float4 wv = *(const float4*)(Wbase);
        #pragma unroll
        for (int i = 0; i < 4; i++) {
            As[0][akq + i][arow]     = (&a0.x)[i];
            As[0][akq + 4 + i][arow] = (&a1.x)[i];
            Ws[0][wkq + i][wrow]     = (&wv.x)[i];
        }
    }
    __syncthreads();

    int buf = 0;
    for (int k0 = 0; k0 < K; k0 += BK) {
        float4 na0, na1, nwv;
        const bool more = (k0 + BK) < K;
        if (more) {
            na0 = *(const float4*)(Abase + k0 + BK);
            na1 = *(const float4*)(Abase + k0 + BK + 4);
            nwv = *(const float4*)(Wbase + k0 + BK);
        }

        #pragma unroll
        for (int kk = 0; kk < BK; kk++) {
            const ulonglong2* ap2 = (const ulonglong2*)&As[buf][kk][ty * 8];
            ulonglong2 aA = ap2[0];
            ulonglong2 aB = ap2[1];
            unsigned long long ap[4] = { aA.x, aA.y, aB.x, aB.y };
            float4 w4 = *(const float4*)&Ws[buf][kk][tx * 4];
            float wn[4] = {w4.x, w4.y, w4.z, w4.w};
            #pragma unroll
            for (int j = 0; j < 4; j++) {
                unsigned long long wd = pk2(wn[j], wn[j]);
                #pragma unroll
                for (int p = 0; p < 4; p++) fma2(acc[p][j], ap[p], wd);
            }
        }

        if (more) {
            const int nb = buf ^ 1;
            #pragma unroll
            for (int i = 0; i < 4; i++) {
                As[nb][akq + i][arow]     = (&na0.x)[i];
                As[nb][akq + 4 + i][arow] = (&na1.x)[i];
                Ws[nb][wkq + i][wrow]     = (&nwv.x)[i];
            }
            __syncthreads();
        }
        buf ^= 1;
    }

    float4 bv = *(const float4*)&bias1[n0 + tx * 4];
    if (bias2) {
        float4 b2 = *(const float4*)&bias2[n0 + tx * 4];
        bv.x += b2.x; bv.y += b2.y; bv.z += b2.z; bv.w += b2.w;
    }
    float bn[4] = {bv.x, bv.y, bv.z, bv.w};

    #pragma unroll
    for (int p = 0; p < 4; p++) {
        float2 u0 = upk(acc[p][0]), u1 = upk(acc[p][1]);
        float2 u2 = upk(acc[p][2]), u3 = upk(acc[p][3]);
        float4 lo = {u0.x + bn[0], u1.x + bn[1], u2.x + bn[2], u3.x + bn[3]};
        float4 hi = {u0.y + bn[0], u1.y + bn[1], u2.y + bn[2], u3.y + bn[3]};
        if (RELU) {
            lo.x = fmaxf(lo.x, 0.f); lo.y = fmaxf(lo.y, 0.f);
            lo.z = fmaxf(lo.z, 0.f); lo.w = fmaxf(lo.w, 0.f);
            hi.x = fmaxf(hi.x, 0.f); hi.y = fmaxf(hi.y, 0.f);
            hi.z = fmaxf(hi.z, 0.f); hi.w = fmaxf(hi.w, 0.f);
        }
        *(float4*)&C[(size_t)(m0 + ty * 8 + 2 * p)     * N + n0 + tx * 4] = lo;
        *(float4*)&C[(size_t)(m0 + ty * 8 + 2 * p + 1) * N + n0 + tx * 4] = hi;
    }
}

template<bool RELU>
__global__ void __launch_bounds__(256)
sgemm128(const float* __restrict__ A, const float* __restrict__ W,
         const float* __restrict__ bias1, const float* __restrict__ bias2,
         float* __restrict__ C, int M, int N, int K)
{
    sgemm128_body<RELU>(A, W, bias1, bias2, C, M, N, K, blockIdx.x, blockIdx.y);
}

// fused act0/val0 head GEMM: blockIdx.z selects (W, bias, C)
__global__ void __launch_bounds__(256)
sgemm128_dual(const float* __restrict__ A,
              const float* __restrict__ Wa, const float* __restrict__ ba, float* __restrict__ Ca,
              const float* __restrict__ Wv, const float* __restrict__ bv, float* __restrict__ Cv,
              int M, int N, int K)
{
    const float* W = blockIdx.z ? Wv : Wa;
    const float* b = blockIdx.z ? bv : ba;
    float*       C = blockIdx.z ? Cv : Ca;
    sgemm128_body<true>(A, W, b, nullptr, C, M, N, K, blockIdx.x, blockIdx.y);
}

// ---------------- init barrier (one-shot) ----------------
__device__ __forceinline__ void grid_bar_init(int tid) {
    __syncthreads();
    if (tid == 0) flag_release(&g_flags[blockIdx.x], 1u);
    if (tid < NBLK) {
        while (__ldcg(&g_flags[tid]) < 1u) __nanosleep(8);
    }
    __syncthreads();
}

// ---------------- persistent LSTM recurrence, weights in registers ----------------
// Flag protocol: flags[bid] = t+2 means block bid completed step t (h(t) stored,
// published via release-exch). Step-t staging requires this warp's 16 producers
// >= t+1. WAR safety for overwriting h(t-2): the 8 warps' forward waits jointly
// cover ALL 128 flags >= t+1, and the post-compute __syncthreads orders those
// polls before any h(t) store — no separate WAR check needed.
#define HST_F  (8 * 32 * 128)
#define RED_F  (8 * 32 * 33 + 32)
#define RSMEM_BYTES ((HST_F + RED_F) * 4)

__global__ void __launch_bounds__(256, 1)
lstm_persist(const float* __restrict__ Whh, const float* __restrict__ xg,
             float* __restrict__ hA, float* __restrict__ hB, float* __restrict__ hs)
{
    extern __shared__ float sm[];
    float* hst = sm;                    // [warp][32 b][128 k]
    float* red = sm + HST_F;            // [(w*32 + r)*33 + b]

    const int tid  = threadIdx.x;
    const int lane = tid & 31;
    const int w    = tid >> 5;
    const int bid  = blockIdx.x;

    // ---- weight registers: lane = gate-row, warp = K-slice ----
    const int uo   = lane >> 2;
    const int gate = lane & 3;
    const float* wrow = Whh + ((size_t)(gate * NHID + bid * 8 + uo)) * NHID + w * 128;
    ulonglong2 wk[32];
    #pragma unroll
    for (int q = 0; q < 32; q++)
        wk[q] = *(const ulonglong2*)(wrow + q * 4);

    // ---- cell role: thread = (unit u = w, batch b = lane) ----
    const int u = w;
    const int b = lane;
    const int jg = bid * 8 + u;
    float c = 0.0f;
    hA[b * NHID + jg] = 0.0f;

    grid_bar_init(tid);   // all flags = 1 (h(-1) ready)

    float* myh = hst + w * 4096;
    const int myprod = w * 16 + (lane & 15);   // this lane's producer flag

    for (int t = 0; t < T_; t++) {
        const float* hin = (t & 1) ? hB : hA;
        float*       hot = (t & 1) ? hA : hB;
        const unsigned ep = (unsigned)(t + 1);   // producers completed step t-1

        // gate biases (independent of h; issued before any waiting)
        const float* xr = xg + ((size_t)b * T_ + t) * G4 + jg;
        float xi = __ldg(xr);
        float xf = __ldg(xr + NHID);
        float xG = __ldg(xr + 2 * NHID);
        float xo = __ldg(xr + 3 * NHID);

        // ---- forward wait: only THIS warp's 16 producers ----
        while (__ldcg(&g_flags[myprod]) < ep) __nanosleep(8);
        __syncwarp();

        const float* src = hin + w * 128 + lane * 4;

        // stage quarter 0 (batches 0..7)
        {
            float4 v[8];
            #pragma unroll
            for (int i = 0; i < 8; i++)
                v[i] = __ldcg((const float4*)(src + (size_t)i * NHID));
            #pragma unroll
            for (int i = 0; i < 8; i++)
                *(float4*)(myh + i * 128 + lane * 4) = v[i];
        }
        __syncwarp();

        // pipelined quarters
        #pragma unroll 1
        for (int qt = 0; qt < 4; qt++) {
            float4 nv[8];
            if (qt < 3) {
                #pragma unroll
                for (int i = 0; i < 8; i++)
                    nv[i] = __ldcg((const float4*)(src + (size_t)((qt + 1) * 8 + i) * NHID));
            }

            #pragma unroll 1
            for (int bq = 0; bq < 8; bq++) {
                const int bb = qt * 8 + bq;
                const float* hb = myh + bb * 128;
                unsigned long long a0 = 0, a1 = 0;
                #pragma unroll
                for (int q = 0; q < 32; q++) {
                    ulonglong2 hv = *(const ulonglong2*)(hb + q * 4);
                    fma2(a0, wk[q].x, hv.x);
                    fma2(a1, wk[q].y, hv.y);
                }
                float2 p0 = upk(a0), p1 = upk(a1);
                red[(w * 32 + lane) * 33 + bb] = (p0.x + p0.y) + (p1.x + p1.y);
            }

            if (qt < 3) {
                #pragma unroll
                for (int i = 0; i < 8; i++)
                    *(float4*)(myh + ((qt + 1) * 8 + i) * 128 + lane * 4) = nv[i];
                __syncwarp();
            }
        }
        // orders all warps' forward-wait polls (=> all 128 flags >= t+1: WAR safe)
        // and publishes red[] for the reduction.
        __syncthreads();

        // ---- reduce 8 K-partials + cell update ----
        float s0 = 0.f, s1 = 0.f, s2 = 0.f, s3 = 0.f;
        #pragma unroll
        for (int ww = 0; ww < 8; ww++) {
            const float* rb = red + (ww * 32 + u * 4) * 33 + b;
            s0 += rb[0];
            s1 += rb[33];
            s2 += rb[66];
            s3 += rb[99];
        }
        float gi = s0 + xi, gf = s1 + xf, gg = s2 + xG, go = s3 + xo;

        float si = 1.0f / (1.0f + expf(-gi));
        float sf = 1.0f / (1.0f + expf(-gf));
        float so = 1.0f / (1.0f + expf(-go));

        c = sf * c + si * tanhf(gg);
        float h = so * tanhf(c);

        // h for next step + history
        __stcg(&hot[b * NHID + jg], h);
        hs[((size_t)b * T_ + t) * NHID + jg] = h;

        // release-publish: bar.sync creates the block-wide happens-before,
        // tid0's release-exch makes all threads' stores visible gpu-wide.
        __syncthreads();
        if (tid == 0) flag_release(&g_flags[bid], (unsigned)(t + 2));
    }
}

// ---------------- softmax over last dim (64) in place ----------------
__global__ void softmax64(float* __restrict__ logits) {
    const int row  = blockIdx.x * 4 + (threadIdx.x >> 5);
    const int lane = threadIdx.x & 31;
    float* p = logits + (size_t)row * NPOL;
    float v0 = p[lane], v1 = p[lane + 32];
    float m = fmaxf(v0, v1);
    #pragma unroll
    for (int off = 16; off > 0; off >>= 1)
        m = fmaxf(m, __shfl_xor_sync(0xffffffffu, m, off));
    float e0 = expf(v0 - m), e1 = expf(v1 - m);
    float sden = e0 + e1;
    #pragma unroll
    for (int off = 16; off > 0; off >>= 1)
        sden += __shfl_xor_sync(0xffffffffu, sden, off);
    float inv = 1.0f / sden;
    p[lane] = e0 * inv;
    p[lane + 32] = e1 * inv;
}

// ---------------- value head: out[m] = dot(V[m,:512], w) + b[0] ----------------
__global__ void matvec_val(const float* __restrict__ V, const float* __restrict__ w,
                           const float* __restrict__ bias, float* __restrict__ out) {
    const int row  = blockIdx.x * 8 + (threadIdx.x >> 5);
    const int lane = threadIdx.x & 31;
    const float* vr = V + (size_t)row * ACTH;
    float s = 0.0f;
    #pragma unroll
    for (int q = 0; q < 4; q++) {
        int k = q * 128 + lane * 4;
        float4 a = *(const float4*)&vr[k];
        float4 b = *(const float4*)&w[k];
        s = fmaf(a.x, b.x, s); s = fmaf(a.y, b.y, s);
        s = fmaf(a.z, b.z, s); s = fmaf(a.w, b.w, s);
    }
    #pragma unroll
    for (int off = 16; off > 0; off >>= 1)
        s += __shfl_xor_sync(0xffffffffu, s, off);
    if (lane == 0) out[row] = s + bias[0];
}

// ---------------- launch ----------------
extern "C" void kernel_launch(void* const* d_in, const int* in_sizes, int n_in,
                              void* d_out, int out_size) {
    const float* x        = (const float*)d_in[0];
    const float* pre_W0   = (const float*)d_in[1];
    const float* pre_b0   = (const float*)d_in[2];
    const float* pre_W1   = (const float*)d_in[3];
    const float* pre_b1   = (const float*)d_in[4];
    const float* w_ih     = (const float*)d_in[5];
    const float* w_hh     = (const float*)d_in[6];
    const float* b_ih     = (const float*)d_in[7];
    const float* b_hh     = (const float*)d_in[8];
    const float* act_W0   = (const float*)d_in[9];
    const float* act_b0   = (const float*)d_in[10];
    const float* act_W1   = (const float*)d_in[11];
    const float* act_b1   = (const float*)d_in[12];
    const float* val_W0   = (const float*)d_in[13];
    const float* val_b0   = (const float*)d_in[14];
    const float* val_W1   = (const float*)d_in[15];
    const float* val_b1   = (const float*)d_in[16];

    float* out_probs = (float*)d_out;
    float* out_value = (float*)d_out + (size_t)MTOT * NPOL;

    float *pH, *pU, *pXG, *pHS, *pA, *pV, *pHA, *pHB;
    cudaGetSymbolAddress((void**)&pH,  g_h);
    cudaGetSymbolAddress((void**)&pU,  g_u);
    cudaGetSymbolAddress((void**)&pXG, g_xg);
    cudaGetSymbolAddress((void**)&pHS, g_hs);
    cudaGetSymbolAddress((void**)&pA,  g_a);
    cudaGetSymbolAddress((void**)&pV,  g_v);
    cudaGetSymbolAddress((void**)&pHA, g_hstA);
    cudaGetSymbolAddress((void**)&pHB, g_hstB);

    cudaFuncSetAttribute(lstm_persist, cudaFuncAttributeMaxDynamicSharedMemorySize, RSMEM_BYTES);

    reset_flags<<<1, 128>>>();

    // pre_dnn
    sgemm128<true ><<<dim3(PRE_ / BN2, MTOT / BM2), 256>>>(x,  pre_W0, pre_b0, nullptr, pH, MTOT, PRE_, IN_);
    sgemm128<false><<<dim3(LH_  / BN2, MTOT / BM2), 256>>>(pH, pre_W1, pre_b1, nullptr, pU, MTOT, LH_, PRE_);

    // input contribution to gates (+ both biases)
    sgemm128<false><<<dim3(G4 / BN2, MTOT / BM2), 256>>>(pU, w_ih, b_ih, b_hh, pXG, MTOT, G4, LH_);

    // persistent recurrence (one launch for all 512 steps)
    lstm_persist<<<NBLK, 256, RSMEM_BYTES>>>(w_hh, pXG, pHA, pHB, pHS);

    // fused first layers of both heads (relu)
    sgemm128_dual<<<dim3(ACTH / BN2, MTOT / BM2, 2), 256>>>(
        pHS, act_W0, act_b0, pA, val_W0, val_b0, pV, MTOT, ACTH, NHID);

    // policy logits + softmax
    sgemm128<false><<<dim3(NPOL / BN2, MTOT / BM2), 256>>>(pA, act_W1, act_b1, nullptr, out_probs, MTOT, NPOL, ACTH);
    softmax64<<<MTOT / 4, 128>>>(out_probs);

    // value output
    matvec_val<<<MTOT / 8, 256>>>(pV, val_W1, val_b1, out_value);
}